// round 1
// baseline (speedup 1.0000x reference)
#include <cuda_runtime.h>

#define BB 64
#define HH 56
#define WW 56
#define CC 256
#define CO 64
#define NROUTES 4
#define CHUNKS 14
#define ROWS_PER_CHUNK 4
#define X_ELEMS (BB*HH*WW*CO)   // 12,845,056

// scratch (device globals; no allocation allowed)
__device__ float g_part[CHUNKS * 9 * BB * CC];   // ~8.3 MB partial sums
__device__ int   g_route[BB];

// ---------------------------------------------------------------------------
// Kernel 1: per-(b,ci) parity sums over a 4-row chunk. grid (64,14), 256 thr.
// Writes 9 partials per thread -> g_part[chunk][s][b][ci] (coalesced, no atomics)
// ---------------------------------------------------------------------------
__global__ void reduce_kernel(const float* __restrict__ in) {
    const int b     = blockIdx.x;
    const int chunk = blockIdx.y;
    const int ci    = threadIdx.x;

    float t00 = 0.f, t01 = 0.f, t10 = 0.f, t11 = 0.f;
    float r0e = 0.f, r0o = 0.f, c0e = 0.f, c0o = 0.f, crn = 0.f;

    const int r0 = chunk * ROWS_PER_CHUNK;
    const float* base = in + ((size_t)b * HH) * WW * CC + ci;

    #pragma unroll
    for (int i = 0; i < ROWS_PER_CHUNK; i++) {
        const int r = r0 + i;
        const float* row = base + (size_t)r * WW * CC;
        float se = 0.f, so = 0.f;
        #pragma unroll 7
        for (int c2 = 0; c2 < 28; c2++) {
            se += row[(2 * c2) * CC];
            so += row[(2 * c2 + 1) * CC];
        }
        const float v0 = row[0];                 // L1 hit (same line as first load)
        if (r & 1) { t10 += se; t11 += so; c0o += v0; }
        else       { t00 += se; t01 += so; c0e += v0; }
        if (r == 0) { r0e = se; r0o = so; crn = v0; }
    }

    float outv[9] = { t00, t01, t10, t11, r0e, r0o, c0e, c0o, crn };
    #pragma unroll
    for (int s = 0; s < 9; s++)
        g_part[(((size_t)chunk * 9 + s) * BB + b) * CC + ci] = outv[s];
}

// ---------------------------------------------------------------------------
// Kernel 2: one block per batch. Reduce partials, fold BN, contract with
// conv weights, pool-scale, FC, argmax. Writes routing_x + g_route.
// ---------------------------------------------------------------------------
__global__ void route_kernel(const float* __restrict__ gamma,
                             const float* __restrict__ beta,
                             const float* __restrict__ mmean,
                             const float* __restrict__ mvar,
                             const float* __restrict__ convw,   // [3][3][256][64]
                             const float* __restrict__ convb,
                             const float* __restrict__ fcw,     // [64][4]
                             const float* __restrict__ fcb,
                             float* __restrict__ dout) {
    __shared__ float Ssm[9 * CC];
    __shared__ float red[256];
    __shared__ float msm[CO];
    __shared__ float rsm[NROUTES];

    const int b = blockIdx.x;
    const int t = threadIdx.x;

    // --- phase 1: reduce 14 chunk partials per (b, ci=t) ---
    float s[9];
    #pragma unroll
    for (int k = 0; k < 9; k++) s[k] = 0.f;
    for (int chunk = 0; chunk < CHUNKS; chunk++) {
        #pragma unroll
        for (int k = 0; k < 9; k++)
            s[k] += g_part[(((size_t)chunk * 9 + k) * BB + b) * CC + t];
    }
    const float a  = gamma[t] / sqrtf(mvar[t] + 1e-3f);
    const float bc = beta[t] - mmean[t] * a;

    const float T00 = s[0], T01 = s[1], T10 = s[2], T11 = s[3];
    const float R0E = s[4], R0O = s[5], C0E = s[6], C0O = s[7], CRN = s[8];
    // S[kh*3+kw]: tap-grid raw sums reconstructed from parity sums
    float S[9] = { T00, T01, T00 - C0E,
                   T10, T11, T10 - C0O,
                   T00 - R0E, T01 - R0O, T00 - C0E - R0E + CRN };
    const float cnt[9] = { 784.f, 784.f, 756.f, 784.f, 784.f, 756.f,
                           756.f, 756.f, 729.f };
    #pragma unroll
    for (int k = 0; k < 9; k++)
        Ssm[k * CC + t] = a * S[k] + bc * cnt[k];
    __syncthreads();

    // --- phase 2: m[co] = (1/784) sum_{ci,k} w[k][ci][co] * Sbn[k][ci] + convb ---
    const int co = t & 63;
    const int g  = t >> 6;           // 4 groups of 64 channels
    float acc = 0.f;
    for (int ci = g * 64; ci < g * 64 + 64; ci++) {
        #pragma unroll
        for (int k = 0; k < 9; k++)
            acc += convw[((size_t)k * CC + ci) * CO + co] * Ssm[k * CC + ci];
    }
    red[t] = acc;
    __syncthreads();
    if (t < CO) {
        float m = (red[t] + red[t + 64] + red[t + 128] + red[t + 192])
                  * (1.0f / 784.0f) + convb[t];
        msm[t] = m;
    }
    __syncthreads();

    // --- phase 3: FC + argmax ---
    if (t < NROUTES) {
        float rv = fcb[t];
        #pragma unroll 8
        for (int c = 0; c < CO; c++)
            rv += msm[c] * fcw[c * NROUTES + t];
        rsm[t] = rv;
        dout[(size_t)X_ELEMS + b * NROUTES + t] = rv;
    }
    __syncthreads();
    if (t == 0) {
        int best = 0; float bv = rsm[0];
        #pragma unroll
        for (int r = 1; r < NROUTES; r++)
            if (rsm[r] > bv) { bv = rsm[r]; best = r; }
        g_route[b] = best;
    }
}

// ---------------------------------------------------------------------------
// Kernel 3: gather selected 64 channels per batch. float4 in/out, coalesced.
// 64*3136 pixels * 16 float4 each.
// ---------------------------------------------------------------------------
__global__ void gather_kernel(const float4* __restrict__ in,
                              float4* __restrict__ out) {
    const int idx = blockIdx.x * blockDim.x + threadIdx.x;
    const int p = idx >> 4;          // pixel index (b*3136 + hw)
    const int j = idx & 15;          // float4 within 64 selected channels
    const int b = p / (HH * WW);
    const int rt = g_route[b];
    out[(size_t)p * 16 + j] = in[(size_t)p * 64 + rt * 16 + j];
}

// ---------------------------------------------------------------------------
extern "C" void kernel_launch(void* const* d_in, const int* in_sizes, int n_in,
                              void* d_out, int out_size) {
    const float* inputs = (const float*)d_in[0];
    const float* gamma  = (const float*)d_in[1];
    const float* beta   = (const float*)d_in[2];
    const float* mmean  = (const float*)d_in[3];
    const float* mvar   = (const float*)d_in[4];
    const float* convw  = (const float*)d_in[5];
    const float* convb  = (const float*)d_in[6];
    const float* fcw    = (const float*)d_in[7];
    const float* fcb    = (const float*)d_in[8];
    float* out = (float*)d_out;

    reduce_kernel<<<dim3(BB, CHUNKS), CC>>>(inputs);
    route_kernel<<<BB, 256>>>(gamma, beta, mmean, mvar, convw, convb, fcw, fcb, out);
    gather_kernel<<<(BB * HH * WW * 16) / 256, 256>>>((const float4*)inputs,
                                                      (float4*)d_out);
}

// round 2
// speedup vs baseline: 1.0862x; 1.0862x over previous
#include <cuda_runtime.h>

#define BB 64
#define HH 56
#define WW 56
#define CC 256
#define CO 64
#define NROUTES 4
#define CHUNKS 14
#define X_ELEMS (BB*HH*WW*CO)   // 12,845,056

// scratch (device globals; no allocation allowed)
__device__ float g_part[CHUNKS * 9 * BB * CC];   // 8.26 MB partial sums
__device__ float g_w2[9 * CC * NROUTES];          // conv_w @ fc_w / 784
__device__ float g_const[NROUTES];                // conv_b @ fc_w + fc_b
__device__ int   g_route[BB];

// ---------------------------------------------------------------------------
// Kernel 0: W2[k][ci][r] = (1/784) * sum_co convw[k][ci][co] * fcw[co][r]
// grid 10: blocks 0..8 = k, block 9 computes g_const.
// ---------------------------------------------------------------------------
__global__ void w2_kernel(const float* __restrict__ convw,
                          const float* __restrict__ convb,
                          const float* __restrict__ fcw,
                          const float* __restrict__ fcb) {
    __shared__ float fsm[CO * NROUTES];
    const int t = threadIdx.x;
    if (t < CO * NROUTES) fsm[t] = fcw[t];
    __syncthreads();

    const int k = blockIdx.x;
    if (k < 9) {
        const int ci = t;
        const float* wrow = convw + ((size_t)k * CC + ci) * CO;
        float acc[NROUTES] = {0.f, 0.f, 0.f, 0.f};
        #pragma unroll 8
        for (int co = 0; co < CO; co++) {
            const float w = wrow[co];
            #pragma unroll
            for (int r = 0; r < NROUTES; r++)
                acc[r] += w * fsm[co * NROUTES + r];
        }
        #pragma unroll
        for (int r = 0; r < NROUTES; r++)
            g_w2[(k * CC + ci) * NROUTES + r] = acc[r] * (1.0f / 784.0f);
    } else if (t < NROUTES) {
        float c = fcb[t];
        for (int co = 0; co < CO; co++)
            c += convb[co] * fsm[co * NROUTES + t];
        g_const[t] = c;
    }
}

// ---------------------------------------------------------------------------
// Kernel 1: parity sums. grid (64,14), 256 threads.
// Each 64-thread group handles one row (float4 = 4 channels per thread).
// smem reduction across the 4 rows, coalesced partial write.
// ---------------------------------------------------------------------------
__global__ void reduce_kernel(const float4* __restrict__ in) {
    const int b     = blockIdx.x;
    const int chunk = blockIdx.y;
    const int t     = threadIdx.x;
    const int row_i = t >> 6;        // 0..3 (global row parity = row_i & 1)
    const int cq    = t & 63;        // channel quad (4 channels)
    const int r     = chunk * 4 + row_i;

    const float4* row = in + ((size_t)(b * HH + r) * WW) * (CC / 4) + cq;

    float4 se = make_float4(0.f, 0.f, 0.f, 0.f);
    float4 so = make_float4(0.f, 0.f, 0.f, 0.f);
    const float4 v0 = row[0];
    #pragma unroll 7
    for (int p = 0; p < 28; p++) {
        const float4 e = row[(size_t)(2 * p)     * (CC / 4)];
        const float4 o = row[(size_t)(2 * p + 1) * (CC / 4)];
        se.x += e.x; se.y += e.y; se.z += e.z; se.w += e.w;
        so.x += o.x; so.y += o.y; so.z += o.z; so.w += o.w;
    }

    // smem: [row][slot(se,so,v0)][256 ch]
    __shared__ float sm[4 * 3 * CC];
    float4* smv = (float4*)sm;
    smv[(row_i * 3 + 0) * 64 + cq] = se;
    smv[(row_i * 3 + 1) * 64 + cq] = so;
    smv[(row_i * 3 + 2) * 64 + cq] = v0;
    __syncthreads();

    const int ch = t;
    #define SM(row, slot) sm[((row) * 3 + (slot)) * CC + ch]
    const float se0 = SM(0,0), se1 = SM(1,0), se2 = SM(2,0), se3 = SM(3,0);
    const float so0 = SM(0,1), so1 = SM(1,1), so2 = SM(2,1), so3 = SM(3,1);
    const float v00 = SM(0,2), v01 = SM(1,2), v02 = SM(2,2), v03 = SM(3,2);
    #undef SM

    const float zf = (chunk == 0) ? 1.f : 0.f;
    float outv[9];
    outv[0] = se0 + se2;        // t00 (even row, even col)
    outv[1] = so0 + so2;        // t01
    outv[2] = se1 + se3;        // t10
    outv[3] = so1 + so3;        // t11
    outv[4] = zf * se0;         // r0e
    outv[5] = zf * so0;         // r0o
    outv[6] = v00 + v02;        // c0e
    outv[7] = v01 + v03;        // c0o
    outv[8] = zf * v00;         // crn

    #pragma unroll
    for (int s = 0; s < 9; s++)
        g_part[(((size_t)chunk * 9 + s) * BB + b) * CC + ch] = outv[s];
}

// ---------------------------------------------------------------------------
// Kernel 2: per-batch routing. 64 blocks x 256 threads (thread = ci).
// Reduce partials, fold BN, contract with W2, block-reduce, argmax.
// ---------------------------------------------------------------------------
__global__ void route_kernel(const float* __restrict__ gamma,
                             const float* __restrict__ beta,
                             const float* __restrict__ mmean,
                             const float* __restrict__ mvar,
                             float* __restrict__ dout) {
    const int b = blockIdx.x;
    const int t = threadIdx.x;   // ci

    float s[9];
    #pragma unroll
    for (int k = 0; k < 9; k++) s[k] = 0.f;
    for (int chunk = 0; chunk < CHUNKS; chunk++) {
        #pragma unroll
        for (int k = 0; k < 9; k++)
            s[k] += g_part[(((size_t)chunk * 9 + k) * BB + b) * CC + t];
    }
    const float a  = gamma[t] * rsqrtf(mvar[t] + 1e-3f);
    const float bc = beta[t] - mmean[t] * a;

    const float T00 = s[0], T01 = s[1], T10 = s[2], T11 = s[3];
    const float R0E = s[4], R0O = s[5], C0E = s[6], C0O = s[7], CRN = s[8];
    const float S[9] = { T00, T01, T00 - C0E,
                         T10, T11, T10 - C0O,
                         T00 - R0E, T01 - R0O, T00 - C0E - R0E + CRN };
    const float cnt[9] = { 784.f, 784.f, 756.f, 784.f, 784.f, 756.f,
                           756.f, 756.f, 729.f };

    float4 acc = make_float4(0.f, 0.f, 0.f, 0.f);
    #pragma unroll
    for (int k = 0; k < 9; k++) {
        const float sbn = a * S[k] + bc * cnt[k];
        const float4 w = *(const float4*)&g_w2[(k * CC + t) * NROUTES];
        acc.x += sbn * w.x; acc.y += sbn * w.y;
        acc.z += sbn * w.z; acc.w += sbn * w.w;
    }

    __shared__ float4 red[256];
    red[t] = acc;
    __syncthreads();
    for (int off = 128; off >= 1; off >>= 1) {
        if (t < off) {
            float4 o = red[t + off];
            red[t].x += o.x; red[t].y += o.y; red[t].z += o.z; red[t].w += o.w;
        }
        __syncthreads();
    }
    if (t == 0) {
        float rv[NROUTES] = { red[0].x + g_const[0], red[0].y + g_const[1],
                              red[0].z + g_const[2], red[0].w + g_const[3] };
        int best = 0; float bv = rv[0];
        #pragma unroll
        for (int r = 1; r < NROUTES; r++)
            if (rv[r] > bv) { bv = rv[r]; best = r; }
        g_route[b] = best;
        #pragma unroll
        for (int r = 0; r < NROUTES; r++)
            dout[(size_t)X_ELEMS + b * NROUTES + r] = rv[r];
    }
}

// ---------------------------------------------------------------------------
// Kernel 3: gather selected 64 channels per batch. float4, coalesced.
// ---------------------------------------------------------------------------
__global__ void gather_kernel(const float4* __restrict__ in,
                              float4* __restrict__ out) {
    const int idx = blockIdx.x * blockDim.x + threadIdx.x;
    const int p = idx >> 4;          // pixel index (b*3136 + hw)
    const int j = idx & 15;          // float4 within 64 selected channels
    const int b = p / (HH * WW);
    const int rt = g_route[b];
    out[(size_t)p * 16 + j] = in[(size_t)p * 64 + rt * 16 + j];
}

// ---------------------------------------------------------------------------
extern "C" void kernel_launch(void* const* d_in, const int* in_sizes, int n_in,
                              void* d_out, int out_size) {
    const float* inputs = (const float*)d_in[0];
    const float* gamma  = (const float*)d_in[1];
    const float* beta   = (const float*)d_in[2];
    const float* mmean  = (const float*)d_in[3];
    const float* mvar   = (const float*)d_in[4];
    const float* convw  = (const float*)d_in[5];
    const float* convb  = (const float*)d_in[6];
    const float* fcw    = (const float*)d_in[7];
    const float* fcb    = (const float*)d_in[8];
    float* out = (float*)d_out;

    w2_kernel<<<10, 256>>>(convw, convb, fcw, fcb);
    reduce_kernel<<<dim3(BB, CHUNKS), 256>>>((const float4*)inputs);
    route_kernel<<<BB, 256>>>(gamma, beta, mmean, mvar, out);
    gather_kernel<<<(BB * HH * WW * 16) / 256, 256>>>((const float4*)inputs,
                                                      (float4*)out);
}

// round 3
// speedup vs baseline: 1.5065x; 1.3870x over previous
#include <cuda_runtime.h>

#define BB 64
#define HH 56
#define WW 56
#define CC 256
#define CO 64
#define NROUTES 4
#define CHUNKS 14
#define X_ELEMS (BB*HH*WW*CO)   // 12,845,056

// scratch (device globals; no allocation allowed)
__device__ float g_part[CHUNKS * 9 * BB * CC];   // 8.26 MB partial sums
__device__ float g_w2[9 * CC * NROUTES];          // conv_w @ fc_w / 784
__device__ float g_const[NROUTES];                // conv_b @ fc_w + fc_b
__device__ int   g_route[BB];

// ---------------------------------------------------------------------------
// w2 slice: W2[k][ci][r] = (1/784) * sum_co convw[k][ci][co] * fcw[co][r]
// ---------------------------------------------------------------------------
__device__ __forceinline__ void w2_work(int k,
                                        const float* __restrict__ convw,
                                        const float* __restrict__ convb,
                                        const float* __restrict__ fcw,
                                        const float* __restrict__ fcb,
                                        float* fsm) {
    const int t = threadIdx.x;
    if (t < CO * NROUTES) fsm[t] = fcw[t];
    __syncthreads();

    if (k < 9) {
        const int ci = t;
        const float* wrow = convw + ((size_t)k * CC + ci) * CO;
        float acc[NROUTES] = {0.f, 0.f, 0.f, 0.f};
        #pragma unroll 8
        for (int co = 0; co < CO; co++) {
            const float w = wrow[co];
            #pragma unroll
            for (int r = 0; r < NROUTES; r++)
                acc[r] += w * fsm[co * NROUTES + r];
        }
        #pragma unroll
        for (int r = 0; r < NROUTES; r++)
            g_w2[(k * CC + ci) * NROUTES + r] = acc[r] * (1.0f / 784.0f);
    } else if (t < NROUTES) {
        float c = fcb[t];
        for (int co = 0; co < CO; co++)
            c += convb[co] * fsm[co * NROUTES + t];
        g_const[t] = c;
    }
}

// ---------------------------------------------------------------------------
// Kernel 1: parity sums (+ merged w2 blocks at blockIdx.y == CHUNKS).
// grid (64, 15), 256 threads. Reduce blocks: each 64-thread group handles one
// row (float4 = 4 channels per thread); smem reduce across 4 rows.
// ---------------------------------------------------------------------------
__global__ void reduce_kernel(const float4* __restrict__ in,
                              const float* __restrict__ convw,
                              const float* __restrict__ convb,
                              const float* __restrict__ fcw,
                              const float* __restrict__ fcb) {
    __shared__ float sm[4 * 3 * CC];

    const int chunk = blockIdx.y;
    if (chunk == CHUNKS) {                 // w2 duty blocks
        if (blockIdx.x < 10)
            w2_work(blockIdx.x, convw, convb, fcw, fcb, sm);
        return;
    }

    const int b     = blockIdx.x;
    const int t     = threadIdx.x;
    const int row_i = t >> 6;        // 0..3
    const int cq    = t & 63;        // channel quad
    const int r     = chunk * 4 + row_i;

    const float4* row = in + ((size_t)(b * HH + r) * WW) * (CC / 4) + cq;

    float4 se = make_float4(0.f, 0.f, 0.f, 0.f);
    float4 so = make_float4(0.f, 0.f, 0.f, 0.f);
    const float4 v0 = row[0];
    #pragma unroll 7
    for (int p = 0; p < 28; p++) {
        const float4 e = row[(size_t)(2 * p)     * (CC / 4)];
        const float4 o = row[(size_t)(2 * p + 1) * (CC / 4)];
        se.x += e.x; se.y += e.y; se.z += e.z; se.w += e.w;
        so.x += o.x; so.y += o.y; so.z += o.z; so.w += o.w;
    }

    float4* smv = (float4*)sm;
    smv[(row_i * 3 + 0) * 64 + cq] = se;
    smv[(row_i * 3 + 1) * 64 + cq] = so;
    smv[(row_i * 3 + 2) * 64 + cq] = v0;
    __syncthreads();

    const int ch = t;
    #define SM(row, slot) sm[((row) * 3 + (slot)) * CC + ch]
    const float se0 = SM(0,0), se1 = SM(1,0), se2 = SM(2,0), se3 = SM(3,0);
    const float so0 = SM(0,1), so1 = SM(1,1), so2 = SM(2,1), so3 = SM(3,1);
    const float v00 = SM(0,2), v01 = SM(1,2), v02 = SM(2,2), v03 = SM(3,2);
    #undef SM

    const float zf = (chunk == 0) ? 1.f : 0.f;
    float outv[9];
    outv[0] = se0 + se2;        // t00 (even row, even col)
    outv[1] = so0 + so2;        // t01
    outv[2] = se1 + se3;        // t10
    outv[3] = so1 + so3;        // t11
    outv[4] = zf * se0;         // r0e
    outv[5] = zf * so0;         // r0o
    outv[6] = v00 + v02;        // c0e
    outv[7] = v01 + v03;        // c0o
    outv[8] = zf * v00;         // crn

    #pragma unroll
    for (int s = 0; s < 9; s++)
        g_part[(((size_t)chunk * 9 + s) * BB + b) * CC + ch] = outv[s];
}

// ---------------------------------------------------------------------------
// Kernel 2: per-batch routing. 64 blocks x 256 threads (thread = ci).
// ---------------------------------------------------------------------------
__global__ void route_kernel(const float* __restrict__ gamma,
                             const float* __restrict__ beta,
                             const float* __restrict__ mmean,
                             const float* __restrict__ mvar,
                             float* __restrict__ dout) {
    const int b = blockIdx.x;
    const int t = threadIdx.x;   // ci

    float s[9];
    #pragma unroll
    for (int k = 0; k < 9; k++) s[k] = 0.f;
    for (int chunk = 0; chunk < CHUNKS; chunk++) {
        #pragma unroll
        for (int k = 0; k < 9; k++)
            s[k] += g_part[(((size_t)chunk * 9 + k) * BB + b) * CC + t];
    }
    const float a  = gamma[t] * rsqrtf(mvar[t] + 1e-3f);
    const float bc = beta[t] - mmean[t] * a;

    const float T00 = s[0], T01 = s[1], T10 = s[2], T11 = s[3];
    const float R0E = s[4], R0O = s[5], C0E = s[6], C0O = s[7], CRN = s[8];
    const float S[9] = { T00, T01, T00 - C0E,
                         T10, T11, T10 - C0O,
                         T00 - R0E, T01 - R0O, T00 - C0E - R0E + CRN };
    const float cnt[9] = { 784.f, 784.f, 756.f, 784.f, 784.f, 756.f,
                           756.f, 756.f, 729.f };

    float4 acc = make_float4(0.f, 0.f, 0.f, 0.f);
    #pragma unroll
    for (int k = 0; k < 9; k++) {
        const float sbn = a * S[k] + bc * cnt[k];
        const float4 w = *(const float4*)&g_w2[(k * CC + t) * NROUTES];
        acc.x += sbn * w.x; acc.y += sbn * w.y;
        acc.z += sbn * w.z; acc.w += sbn * w.w;
    }

    __shared__ float4 red[256];
    red[t] = acc;
    __syncthreads();
    for (int off = 128; off >= 32; off >>= 1) {
        if (t < off) {
            float4 o = red[t + off];
            red[t].x += o.x; red[t].y += o.y; red[t].z += o.z; red[t].w += o.w;
        }
        __syncthreads();
    }
    if (t < 32) {
        float4 v = red[t];
        #pragma unroll
        for (int off = 16; off >= 1; off >>= 1) {
            v.x += __shfl_down_sync(0xffffffffu, v.x, off);
            v.y += __shfl_down_sync(0xffffffffu, v.y, off);
            v.z += __shfl_down_sync(0xffffffffu, v.z, off);
            v.w += __shfl_down_sync(0xffffffffu, v.w, off);
        }
        if (t == 0) {
            float rv[NROUTES] = { v.x + g_const[0], v.y + g_const[1],
                                  v.z + g_const[2], v.w + g_const[3] };
            int best = 0; float bv = rv[0];
            #pragma unroll
            for (int r = 1; r < NROUTES; r++)
                if (rv[r] > bv) { bv = rv[r]; best = r; }
            g_route[b] = best;
            #pragma unroll
            for (int r = 0; r < NROUTES; r++)
                dout[(size_t)X_ELEMS + b * NROUTES + r] = rv[r];
        }
    }
}

// ---------------------------------------------------------------------------
// Kernel 3: gather. grid (49, 64): y = batch (no divide), 4 float4 per
// thread, front-batched loads (MLP=4), coalesced 256B segments.
// ---------------------------------------------------------------------------
__global__ void gather_kernel(const float4* __restrict__ in,
                              float4* __restrict__ out) {
    const int b = blockIdx.y;
    const int rt16 = g_route[b] * 16;
    const size_t bbase = (size_t)b * (HH * WW) * 16;   // in float4 units of x

    const int f0 = blockIdx.x * 1024 + threadIdx.x;
    float4 v[4];
    #pragma unroll
    for (int i = 0; i < 4; i++) {
        const int f = f0 + i * 256;
        const int p = f >> 4;
        const int j = f & 15;
        v[i] = __ldg(&in[bbase * 4 + (size_t)p * 64 + rt16 + j]);
    }
    #pragma unroll
    for (int i = 0; i < 4; i++)
        out[bbase + f0 + i * 256] = v[i];
}

// ---------------------------------------------------------------------------
extern "C" void kernel_launch(void* const* d_in, const int* in_sizes, int n_in,
                              void* d_out, int out_size) {
    const float* inputs = (const float*)d_in[0];
    const float* gamma  = (const float*)d_in[1];
    const float* beta   = (const float*)d_in[2];
    const float* mmean  = (const float*)d_in[3];
    const float* mvar   = (const float*)d_in[4];
    const float* convw  = (const float*)d_in[5];
    const float* convb  = (const float*)d_in[6];
    const float* fcw    = (const float*)d_in[7];
    const float* fcb    = (const float*)d_in[8];
    float* out = (float*)d_out;

    reduce_kernel<<<dim3(BB, CHUNKS + 1), 256>>>((const float4*)inputs,
                                                 convw, convb, fcw, fcb);
    route_kernel<<<BB, 256>>>(gamma, beta, mmean, mvar, out);
    gather_kernel<<<dim3(49, BB), 256>>>((const float4*)inputs, (float4*)out);
}